// round 1
// baseline (speedup 1.0000x reference)
#include <cuda_runtime.h>
#include <math.h>

#define N_NODES 50000
#define N_EDGES 320000
#define D       128
#define HID     512
#define KN      256
#define KE      384
#define EPSV    1e-5f
#define STAT_BLOCKS 256

// ---------------- device scratch (allocation-free: static globals) ----------
__device__ float g_msg[(size_t)N_NODES * D];            // 25.6 MB
__device__ float g_H[(size_t)N_EDGES * HID];            // 655 MB (hidden acts, reused node/edge)
__device__ float g_W1p[(size_t)KE * HID];               // folded W1 (max 384x512)
__device__ float g_b1p[HID];
__device__ float g_scale[KE];
__device__ float g_shift[KE];
__device__ float g_psum[(size_t)STAT_BLOCKS * KE];
__device__ float g_psq [(size_t)STAT_BLOCKS * KE];

// ---------------- zero the message buffer -----------------------------------
__global__ void zero_msg_kernel() {
    int i = blockIdx.x * blockDim.x + threadIdx.x;
    if (i < N_NODES * D / 4) ((float4*)g_msg)[i] = make_float4(0.f, 0.f, 0.f, 0.f);
}

// ---------------- scatter-add edges into msg by dst --------------------------
__global__ void scatter_kernel(const float* __restrict__ edges,
                               const int* __restrict__ graph) {
    long idx = (long)blockIdx.x * blockDim.x + threadIdx.x;
    if (idx >= (long)N_EDGES * D) return;
    int e = (int)(idx >> 7);
    int c = (int)(idx & 127);
    int d = __ldg(&graph[N_EDGES + e]);   // dst
    atomicAdd(&g_msg[(long)d * D + c], edges[idx]);
}

// ---------------- batchnorm stats: node input [N, 256] -----------------------
__global__ void node_stats_partial(const float* __restrict__ nodes) {
    int col = threadIdx.x;   // 0..255
    float s = 0.f, q = 0.f;
    for (int r = blockIdx.x; r < N_NODES; r += gridDim.x) {
        float v = (col < D) ? nodes[(long)r * D + col]
                            : g_msg[(long)r * D + (col - D)];
        s += v; q += v * v;
    }
    g_psum[(long)blockIdx.x * KN + col] = s;
    g_psq [(long)blockIdx.x * KN + col] = q;
}

// ---------------- batchnorm stats: edge input [E, 384] -----------------------
__global__ void edge_stats_partial(const float* __restrict__ nodesOut,
                                   const float* __restrict__ edges,
                                   const int* __restrict__ graph) {
    int col = threadIdx.x;   // 0..383
    float s = 0.f, q = 0.f;
    for (int r = blockIdx.x; r < N_EDGES; r += gridDim.x) {
        float v;
        if (col < D) {
            int si = __ldg(&graph[r]);
            v = nodesOut[(long)si * D + col];
        } else if (col < 2 * D) {
            int di = __ldg(&graph[N_EDGES + r]);
            v = nodesOut[(long)di * D + (col - D)];
        } else {
            v = edges[(long)r * D + (col - 2 * D)];
        }
        s += v; q += v * v;
    }
    g_psum[(long)blockIdx.x * KE + col] = s;
    g_psq [(long)blockIdx.x * KE + col] = q;
}

// ---------------- finalize stats -> per-column scale/shift -------------------
__global__ void stats_finalize(int ncols, float inv_count,
                               const float* __restrict__ w,
                               const float* __restrict__ b) {
    int col = threadIdx.x;
    if (col >= ncols) return;
    float s = 0.f, q = 0.f;
    for (int bk = 0; bk < STAT_BLOCKS; bk++) {
        s += g_psum[(long)bk * ncols + col];
        q += g_psq [(long)bk * ncols + col];
    }
    float mean = s * inv_count;
    float var  = fmaxf(q * inv_count - mean * mean, 0.f);
    float sc   = rsqrtf(var + EPSV) * w[col];
    g_scale[col] = sc;
    g_shift[col] = b[col] - mean * sc;
}

// ---------------- fold batchnorm into W1/b1 ----------------------------------
__global__ void fold_kernel(int K, const float* __restrict__ W1,
                            const float* __restrict__ b1) {
    int j = blockIdx.x * blockDim.x + threadIdx.x;   // 0..511
    if (j >= HID) return;
    float acc = b1[j];
    for (int k = 0; k < K; k++) {
        float wv = W1[(long)k * HID + j];
        acc += g_shift[k] * wv;
        g_W1p[(long)k * HID + j] = wv * g_scale[k];
    }
    g_b1p[j] = acc;
}

// ---------------- GEMM1: H = gelu(X @ W1p + b1p), X implicit -----------------
// MODE 0: node input (K=256): X[m] = [nodes[m], msg[m]]
// MODE 1: edge input (K=384): X[m] = [nodesOut[src[m]], nodesOut[dst[m]], edges[m]]
template <int MODE, int K>
__global__ __launch_bounds__(256)
void gemm1_kernel(const float* __restrict__ nodes,
                  const float* __restrict__ edges,
                  const int*   __restrict__ graph,
                  const float* __restrict__ nodesOut,
                  int M) {
    const int BM = 128, BN = 128, BK = 8, TM = 8, TN = 8;
    __shared__ float As[BK][BM];
    __shared__ float Bs[BK][BN];
    __shared__ int s_src[BM], s_dst[BM];

    int tid = threadIdx.x;
    int cRow = blockIdx.y, cCol = blockIdx.x;
    int rowBase = cRow * BM;

    if (MODE == 1) {
        if (tid < BM) {
            int m = rowBase + tid;
            s_src[tid] = (m < M) ? graph[m] : 0;
            s_dst[tid] = (m < M) ? graph[N_EDGES + m] : 0;
        }
        __syncthreads();
    }

    int aRow = tid >> 1;          // 0..127
    int aCol = (tid & 1) * 4;     // 0 or 4
    int bRow = tid >> 5;          // 0..7
    int bCol = (tid & 31) * 4;    // 0..124
    int tx = tid & 15, ty = tid >> 4;
    int mA = rowBase + aRow;

    float acc[TM][TN];
    #pragma unroll
    for (int i = 0; i < TM; i++)
        #pragma unroll
        for (int j = 0; j < TN; j++) acc[i][j] = 0.f;

    for (int k0 = 0; k0 < K; k0 += BK) {
        float4 av = make_float4(0.f, 0.f, 0.f, 0.f);
        if (mA < M) {
            int k = k0 + aCol;
            const float* p;
            if (MODE == 0) {
                p = (k < D) ? nodes + (long)mA * D + k
                            : g_msg + (long)mA * D + (k - D);
            } else {
                if (k < D)          p = nodesOut + (long)s_src[aRow] * D + k;
                else if (k < 2 * D) p = nodesOut + (long)s_dst[aRow] * D + (k - D);
                else                p = edges    + (long)mA * D + (k - 2 * D);
            }
            av = *(const float4*)p;
        }
        As[aCol + 0][aRow] = av.x;
        As[aCol + 1][aRow] = av.y;
        As[aCol + 2][aRow] = av.z;
        As[aCol + 3][aRow] = av.w;

        float4 bv = *(const float4*)(g_W1p + (long)(k0 + bRow) * HID + cCol * BN + bCol);
        *(float4*)&Bs[bRow][bCol] = bv;
        __syncthreads();

        #pragma unroll
        for (int kk = 0; kk < BK; kk++) {
            float rm[TM], rn[TN];
            #pragma unroll
            for (int i = 0; i < TM; i++) rm[i] = As[kk][ty * TM + i];
            #pragma unroll
            for (int j = 0; j < TN; j++) rn[j] = Bs[kk][tx * TN + j];
            #pragma unroll
            for (int i = 0; i < TM; i++)
                #pragma unroll
                for (int j = 0; j < TN; j++) acc[i][j] += rm[i] * rn[j];
        }
        __syncthreads();
    }

    #pragma unroll
    for (int i = 0; i < TM; i++) {
        int m = rowBase + ty * TM + i;
        if (m >= M) continue;
        #pragma unroll
        for (int j = 0; j < TN; j++) {
            int col = cCol * BN + tx * TN + j;
            float x = acc[i][j] + g_b1p[col];
            float g = 0.5f * x * (1.f + erff(x * 0.70710678118654752f));
            g_H[(long)m * HID + col] = g;
        }
    }
}

// ---------------- GEMM2: out = H @ W2 + b2 + residual ------------------------
__global__ __launch_bounds__(256)
void gemm2_kernel(const float* __restrict__ W2,
                  const float* __restrict__ b2,
                  const float* __restrict__ res,
                  float* __restrict__ out,
                  int M) {
    const int BM = 128, BN = 128, BK = 8, TM = 8, TN = 8;
    const int K = HID;
    __shared__ float As[BK][BM];
    __shared__ float Bs[BK][BN];

    int tid = threadIdx.x;
    int cRow = blockIdx.y;
    int rowBase = cRow * BM;

    int aRow = tid >> 1;
    int aCol = (tid & 1) * 4;
    int bRow = tid >> 5;
    int bCol = (tid & 31) * 4;
    int tx = tid & 15, ty = tid >> 4;
    int mA = rowBase + aRow;

    float acc[TM][TN];
    #pragma unroll
    for (int i = 0; i < TM; i++)
        #pragma unroll
        for (int j = 0; j < TN; j++) acc[i][j] = 0.f;

    for (int k0 = 0; k0 < K; k0 += BK) {
        float4 av = make_float4(0.f, 0.f, 0.f, 0.f);
        if (mA < M) av = *(const float4*)(g_H + (long)mA * HID + k0 + aCol);
        As[aCol + 0][aRow] = av.x;
        As[aCol + 1][aRow] = av.y;
        As[aCol + 2][aRow] = av.z;
        As[aCol + 3][aRow] = av.w;

        float4 bv = *(const float4*)(W2 + (long)(k0 + bRow) * BN + bCol);
        *(float4*)&Bs[bRow][bCol] = bv;
        __syncthreads();

        #pragma unroll
        for (int kk = 0; kk < BK; kk++) {
            float rm[TM], rn[TN];
            #pragma unroll
            for (int i = 0; i < TM; i++) rm[i] = As[kk][ty * TM + i];
            #pragma unroll
            for (int j = 0; j < TN; j++) rn[j] = Bs[kk][tx * TN + j];
            #pragma unroll
            for (int i = 0; i < TM; i++)
                #pragma unroll
                for (int j = 0; j < TN; j++) acc[i][j] += rm[i] * rn[j];
        }
        __syncthreads();
    }

    #pragma unroll
    for (int i = 0; i < TM; i++) {
        int m = rowBase + ty * TM + i;
        if (m >= M) continue;
        #pragma unroll
        for (int j = 0; j < TN; j++) {
            int col = tx * TN + j;
            out[(long)m * D + col] = acc[i][j] + b2[col] + res[(long)m * D + col];
        }
    }
}

// ---------------- launch -----------------------------------------------------
extern "C" void kernel_launch(void* const* d_in, const int* in_sizes, int n_in,
                              void* d_out, int out_size) {
    const float* nodes = (const float*)d_in[0];
    const float* edges = (const float*)d_in[1];
    const int*   graph = (const int*)  d_in[2];
    const float* nnw   = (const float*)d_in[3];
    const float* nnb   = (const float*)d_in[4];
    const float* enw   = (const float*)d_in[5];
    const float* enb   = (const float*)d_in[6];
    const float* Wn1   = (const float*)d_in[7];
    const float* bn1   = (const float*)d_in[8];
    const float* Wn2   = (const float*)d_in[9];
    const float* bn2   = (const float*)d_in[10];
    const float* We1   = (const float*)d_in[11];
    const float* be1   = (const float*)d_in[12];
    const float* We2   = (const float*)d_in[13];
    const float* be2   = (const float*)d_in[14];

    float* out_nodes = (float*)d_out;
    float* out_edges = out_nodes + (long)N_NODES * D;

    // 1) msg = segment_sum(edges, dst)
    zero_msg_kernel<<<(N_NODES * D / 4 + 255) / 256, 256>>>();
    scatter_kernel<<<(int)(((long)N_EDGES * D + 255) / 256), 256>>>(edges, graph);

    // 2) node batchnorm stats -> fold into W1
    node_stats_partial<<<STAT_BLOCKS, KN>>>(nodes);
    stats_finalize<<<1, KE>>>(KN, 1.f / N_NODES, nnw, nnb);
    fold_kernel<<<(HID + 255) / 256, 256>>>(KN, Wn1, bn1);

    // 3) node MLP
    {
        dim3 g1(HID / 128, (N_NODES + 127) / 128);
        gemm1_kernel<0, KN><<<g1, 256>>>(nodes, nullptr, nullptr, nullptr, N_NODES);
        dim3 g2(1, (N_NODES + 127) / 128);
        gemm2_kernel<<<g2, 256>>>(Wn2, bn2, nodes, out_nodes, N_NODES);
    }

    // 4) edge batchnorm stats -> fold into W1
    edge_stats_partial<<<STAT_BLOCKS, KE>>>(out_nodes, edges, graph);
    stats_finalize<<<1, KE>>>(KE, 1.f / N_EDGES, enw, enb);
    fold_kernel<<<(HID + 255) / 256, 256>>>(KE, We1, be1);

    // 5) edge MLP
    {
        dim3 g1(HID / 128, (N_EDGES + 127) / 128);
        gemm1_kernel<1, KE><<<g1, 256>>>(nullptr, edges, graph, out_nodes, N_EDGES);
        dim3 g2(1, (N_EDGES + 127) / 128);
        gemm2_kernel<<<g2, 256>>>(We2, be2, edges, out_edges, N_EDGES);
    }
}

// round 2
// speedup vs baseline: 2.0769x; 2.0769x over previous
#include <cuda_runtime.h>
#include <math.h>

#define N_NODES 50000
#define N_EDGES 320000
#define D       128
#define HID     512
#define KN      256
#define KE      384
#define EPSV    1e-5f
#define STAT_BLOCKS 256

// smem tile geometry (floats)
#define ASZ  (128 * 36)    // A tile: 128 rows x 32 k, pad to 36
#define BSZ  (32 * 136)    // B tile: 32 k x 128 n, pad to 136
#define SMEMF (2*ASZ + 2*BSZ + 128)
#define SMEMB (SMEMF * 4)

// ---------------- device scratch (allocation-free: static globals) ----------
__device__ float g_msg[(size_t)N_NODES * D];            // 25.6 MB
__device__ float g_H[(size_t)N_EDGES * HID];            // 655 MB hidden acts (tf32 bits)
__device__ float g_W1p[(size_t)KE * HID];               // folded W1 (tf32 bits)
__device__ float g_W2t[(size_t)HID * D];                // W2 (tf32 bits)
__device__ float g_b1p[HID];
__device__ float g_scale[KE];
__device__ float g_shift[KE];
__device__ float g_psum[(size_t)STAT_BLOCKS * KE];
__device__ float g_psq [(size_t)STAT_BLOCKS * KE];

// ---------------- helpers ----------------------------------------------------
__device__ __forceinline__ unsigned f2tf(float x) {
    unsigned r;
    asm("cvt.rna.tf32.f32 %0, %1;" : "=r"(r) : "f"(x));
    return r;
}

__device__ __forceinline__ void mma8(float* c, const unsigned* a, const unsigned* b) {
    asm volatile(
        "mma.sync.aligned.m16n8k8.row.col.f32.tf32.tf32.f32 "
        "{%0,%1,%2,%3}, {%4,%5,%6,%7}, {%8,%9}, {%0,%1,%2,%3};\n"
        : "+f"(c[0]), "+f"(c[1]), "+f"(c[2]), "+f"(c[3])
        : "r"(a[0]), "r"(a[1]), "r"(a[2]), "r"(a[3]), "r"(b[0]), "r"(b[1]));
}

__device__ __forceinline__ void cp16(float* smem_dst, const float* gsrc) {
    unsigned s = (unsigned)__cvta_generic_to_shared(smem_dst);
    asm volatile("cp.async.cg.shared.global [%0], [%1], 16;" :: "r"(s), "l"(gsrc));
}
#define CP_COMMIT() asm volatile("cp.async.commit_group;" ::: "memory")
#define CP_WAIT0()  asm volatile("cp.async.wait_group 0;" ::: "memory")

__device__ __forceinline__ float gelu_exact(float x) {
    return 0.5f * x * (1.f + erff(x * 0.70710678118654752f));
}

// fragment compute for one 32-deep k stage: warp tile 32x64
__device__ __forceinline__ void mma_tile(float (&acc)[2][8][4],
                                         const float* sA, const float* sB,
                                         int wm, int wn, int g, int tg) {
    #pragma unroll
    for (int kk = 0; kk < 32; kk += 8) {
        unsigned a[2][4];
        #pragma unroll
        for (int mi = 0; mi < 2; mi++) {
            const float* A0 = sA + (wm + mi*16 + g) * 36 + kk + tg;
            a[mi][0] = __float_as_uint(A0[0]);
            a[mi][1] = __float_as_uint(A0[8*36]);
            a[mi][2] = __float_as_uint(A0[4]);
            a[mi][3] = __float_as_uint(A0[8*36 + 4]);
        }
        unsigned b[8][2];
        #pragma unroll
        for (int ni = 0; ni < 8; ni++) {
            const float* B0 = sB + (kk + tg) * 136 + wn + ni*8 + g;
            b[ni][0] = __float_as_uint(B0[0]);
            b[ni][1] = __float_as_uint(B0[4*136]);
        }
        #pragma unroll
        for (int mi = 0; mi < 2; mi++)
            #pragma unroll
            for (int ni = 0; ni < 8; ni++)
                mma8(acc[mi][ni], a[mi], b[ni]);
    }
}

// ---------------- zero the message buffer -----------------------------------
__global__ void zero_msg_kernel() {
    int i = blockIdx.x * blockDim.x + threadIdx.x;
    if (i < N_NODES * D / 4) ((float4*)g_msg)[i] = make_float4(0.f, 0.f, 0.f, 0.f);
}

// ---------------- scatter-add edges into msg by dst --------------------------
__global__ void scatter_kernel(const float* __restrict__ edges,
                               const int* __restrict__ graph) {
    long idx = (long)blockIdx.x * blockDim.x + threadIdx.x;
    if (idx >= (long)N_EDGES * D) return;
    int e = (int)(idx >> 7);
    int c = (int)(idx & 127);
    int d = __ldg(&graph[N_EDGES + e]);   // dst
    atomicAdd(&g_msg[(long)d * D + c], edges[idx]);
}

// ---------------- batchnorm stats -------------------------------------------
__global__ void node_stats_partial(const float* __restrict__ nodes) {
    int col = threadIdx.x;   // 0..255
    float s = 0.f, q = 0.f;
    for (int r = blockIdx.x; r < N_NODES; r += gridDim.x) {
        float v = (col < D) ? nodes[(long)r * D + col]
                            : g_msg[(long)r * D + (col - D)];
        s += v; q += v * v;
    }
    g_psum[(long)blockIdx.x * KN + col] = s;
    g_psq [(long)blockIdx.x * KN + col] = q;
}

__global__ void edge_stats_partial(const float* __restrict__ nodesOut,
                                   const float* __restrict__ edges,
                                   const int* __restrict__ graph) {
    int col = threadIdx.x;   // 0..383
    float s = 0.f, q = 0.f;
    for (int r = blockIdx.x; r < N_EDGES; r += gridDim.x) {
        float v;
        if (col < D) {
            int si = __ldg(&graph[r]);
            v = nodesOut[(long)si * D + col];
        } else if (col < 2 * D) {
            int di = __ldg(&graph[N_EDGES + r]);
            v = nodesOut[(long)di * D + (col - D)];
        } else {
            v = edges[(long)r * D + (col - 2 * D)];
        }
        s += v; q += v * v;
    }
    g_psum[(long)blockIdx.x * KE + col] = s;
    g_psq [(long)blockIdx.x * KE + col] = q;
}

// parallel finalize: one block per column
__global__ void stats_finalize(int ncols, float inv_count,
                               const float* __restrict__ w,
                               const float* __restrict__ b) {
    __shared__ float rs[STAT_BLOCKS], rq[STAT_BLOCKS];
    int col = blockIdx.x;
    int t = threadIdx.x;
    rs[t] = g_psum[(long)t * ncols + col];
    rq[t] = g_psq [(long)t * ncols + col];
    __syncthreads();
    for (int off = STAT_BLOCKS / 2; off > 0; off >>= 1) {
        if (t < off) { rs[t] += rs[t + off]; rq[t] += rq[t + off]; }
        __syncthreads();
    }
    if (t == 0) {
        float mean = rs[0] * inv_count;
        float var  = fmaxf(rq[0] * inv_count - mean * mean, 0.f);
        float sc   = rsqrtf(var + EPSV) * w[col];
        g_scale[col] = sc;
        g_shift[col] = b[col] - mean * sc;
    }
}

// ---------------- fold batchnorm into W1/b1, round W1 to tf32 ----------------
__global__ void fold_kernel(int K, const float* __restrict__ W1,
                            const float* __restrict__ b1) {
    int j = blockIdx.x * blockDim.x + threadIdx.x;   // 0..511
    if (j >= HID) return;
    float acc = b1[j];
    for (int k = 0; k < K; k++) {
        float wv = W1[(long)k * HID + j];
        acc += g_shift[k] * wv;
        g_W1p[(long)k * HID + j] = __uint_as_float(f2tf(wv * g_scale[k]));
    }
    g_b1p[j] = acc;
}

// ---------------- W2 -> tf32 -------------------------------------------------
__global__ void w2cvt_kernel(const float* __restrict__ W2) {
    int i = blockIdx.x * blockDim.x + threadIdx.x;
    if (i < HID * D) g_W2t[i] = __uint_as_float(f2tf(W2[i]));
}

// ---------------- GEMM1 (tensor core): g_H = gelu(X @ W1p + b1p) -------------
// MODE 0: K=256, X[m] = [nodes[m], msg[m]]
// MODE 1: K=384, X[m] = [nodesOut[src[m]], nodesOut[dst[m]], edges[m]]
template <int MODE, int K>
__global__ __launch_bounds__(256, 2)
void gemm1_tc(const float* __restrict__ nodes,
              const float* __restrict__ edges,
              const int*   __restrict__ graph,
              const float* __restrict__ nodesOut,
              int M) {
    extern __shared__ float sm[];
    float* sA = sm;
    float* sB = sm + 2*ASZ;
    float* sBias = sm + 2*ASZ + 2*BSZ;

    const int tid = threadIdx.x;
    const int lane = tid & 31, wid = tid >> 5;
    const int g = lane >> 2, tg = lane & 3;
    const int wm = (wid & 3) * 32;
    const int wn = (wid >> 2) * 64;
    const int cCol = blockIdx.x;
    const int rowBase = blockIdx.y * 128;

    if (tid < 128) sBias[tid] = g_b1p[cCol * 128 + tid];

    // A load mapping: 2 threads per row, 16 floats each
    const int r = tid >> 1, kb = (tid & 1) * 16;
    const int mA = rowBase + r;
    const int mc = (mA < M) ? mA : (M - 1);
    int vsrc = 0, vdst = 0;
    if (MODE == 1) { vsrc = graph[mA]; vdst = graph[N_EDGES + mA]; }

    // B load mapping: 32 rows x 128 cols, 16 floats per thread
    const int kr = tid >> 3, nb = (tid & 7) * 16;

    float acc[2][8][4];
    #pragma unroll
    for (int i = 0; i < 2; i++)
        #pragma unroll
        for (int j = 0; j < 8; j++)
            #pragma unroll
            for (int c = 0; c < 4; c++) acc[i][j][c] = 0.f;

    unsigned ar[16];

    auto loadA = [&](int k0) {
        int kk0 = k0 + kb;
        int seg = kk0 >> 7, l = kk0 & 127;
        const float* p;
        if (MODE == 0) {
            p = (seg == 0 ? nodes + (long)mc * D : g_msg + (long)mc * D) + l;
        } else {
            p = (seg == 0 ? nodesOut + (long)vsrc * D
               : seg == 1 ? nodesOut + (long)vdst * D
                          : edges + (long)mA * D) + l;
        }
        #pragma unroll
        for (int q = 0; q < 4; q++) {
            float4 v = *(const float4*)(p + 4 * q);
            ar[q*4+0] = f2tf(v.x); ar[q*4+1] = f2tf(v.y);
            ar[q*4+2] = f2tf(v.z); ar[q*4+3] = f2tf(v.w);
        }
    };
    auto issueB = [&](int k0, int pb) {
        float* d = sB + pb * BSZ + kr * 136 + nb;
        const float* s = g_W1p + (long)(k0 + kr) * HID + cCol * 128 + nb;
        #pragma unroll
        for (int q = 0; q < 4; q++) cp16(d + 4*q, s + 4*q);
        CP_COMMIT();
    };
    auto stsA = [&](int pb) {
        float* d = sA + pb * ASZ + r * 36 + kb;
        #pragma unroll
        for (int q = 0; q < 4; q++)
            *(uint4*)(d + 4*q) = make_uint4(ar[q*4+0], ar[q*4+1], ar[q*4+2], ar[q*4+3]);
    };

    issueB(0, 0);
    loadA(0);
    const int S = K / 32;
    for (int s = 0; s < S; s++) {
        int p = s & 1;
        stsA(p);
        CP_WAIT0();
        __syncthreads();
        if (s + 1 < S) { issueB((s + 1) * 32, p ^ 1); loadA((s + 1) * 32); }
        mma_tile(acc, sA + p * ASZ, sB + p * BSZ, wm, wn, g, tg);
    }

    // epilogue: bias + exact gelu, write tf32-rounded to g_H
    #pragma unroll
    for (int mi = 0; mi < 2; mi++) {
        int row0 = rowBase + wm + mi * 16 + g;
        #pragma unroll
        for (int ni = 0; ni < 8; ni++) {
            int c0 = wn + ni * 8 + tg * 2;
            int col = cCol * 128 + c0;
            float b0 = sBias[c0], b1 = sBias[c0 + 1];
            if (row0 < M) {
                g_H[(long)row0 * HID + col]     = __uint_as_float(f2tf(gelu_exact(acc[mi][ni][0] + b0)));
                g_H[(long)row0 * HID + col + 1] = __uint_as_float(f2tf(gelu_exact(acc[mi][ni][1] + b1)));
            }
            if (row0 + 8 < M) {
                g_H[(long)(row0+8) * HID + col]     = __uint_as_float(f2tf(gelu_exact(acc[mi][ni][2] + b0)));
                g_H[(long)(row0+8) * HID + col + 1] = __uint_as_float(f2tf(gelu_exact(acc[mi][ni][3] + b1)));
            }
        }
    }
}

// ---------------- GEMM2 (tensor core): out = g_H @ W2t + b2 + res ------------
__global__ __launch_bounds__(256, 2)
void gemm2_tc(const float* __restrict__ b2,
              const float* __restrict__ res,
              float* __restrict__ out,
              int M) {
    extern __shared__ float sm[];
    float* sA = sm;
    float* sB = sm + 2*ASZ;
    float* sBias = sm + 2*ASZ + 2*BSZ;

    const int tid = threadIdx.x;
    const int lane = tid & 31, wid = tid >> 5;
    const int g = lane >> 2, tg = lane & 3;
    const int wm = (wid & 3) * 32;
    const int wn = (wid >> 2) * 64;
    const int rowBase = blockIdx.y * 128;

    if (tid < 128) sBias[tid] = b2[tid];

    const int r = tid >> 1, kb = (tid & 1) * 16;
    const int mA = rowBase + r;
    const int mc = (mA < M) ? mA : (M - 1);
    const int kr = tid >> 3, nb = (tid & 7) * 16;

    float acc[2][8][4];
    #pragma unroll
    for (int i = 0; i < 2; i++)
        #pragma unroll
        for (int j = 0; j < 8; j++)
            #pragma unroll
            for (int c = 0; c < 4; c++) acc[i][j][c] = 0.f;

    auto issueAB = [&](int k0, int pb) {
        float* dA = sA + pb * ASZ + r * 36 + kb;
        const float* sa = g_H + (long)mc * HID + k0 + kb;
        #pragma unroll
        for (int q = 0; q < 4; q++) cp16(dA + 4*q, sa + 4*q);
        float* dB = sB + pb * BSZ + kr * 136 + nb;
        const float* sb = g_W2t + (long)(k0 + kr) * D + nb;
        #pragma unroll
        for (int q = 0; q < 4; q++) cp16(dB + 4*q, sb + 4*q);
        CP_COMMIT();
    };

    issueAB(0, 0);
    const int S = HID / 32;   // 16
    for (int s = 0; s < S; s++) {
        int p = s & 1;
        CP_WAIT0();
        __syncthreads();
        if (s + 1 < S) issueAB((s + 1) * 32, p ^ 1);
        mma_tile(acc, sA + p * ASZ, sB + p * BSZ, wm, wn, g, tg);
    }

    #pragma unroll
    for (int mi = 0; mi < 2; mi++) {
        int row0 = rowBase + wm + mi * 16 + g;
        #pragma unroll
        for (int ni = 0; ni < 8; ni++) {
            int col = wn + ni * 8 + tg * 2;
            float b0 = sBias[col], b1 = sBias[col + 1];
            if (row0 < M) {
                long o = (long)row0 * D + col;
                out[o]     = acc[mi][ni][0] + b0 + res[o];
                out[o + 1] = acc[mi][ni][1] + b1 + res[o + 1];
            }
            if (row0 + 8 < M) {
                long o = (long)(row0 + 8) * D + col;
                out[o]     = acc[mi][ni][2] + b0 + res[o];
                out[o + 1] = acc[mi][ni][3] + b1 + res[o + 1];
            }
        }
    }
}

// ---------------- launch -----------------------------------------------------
extern "C" void kernel_launch(void* const* d_in, const int* in_sizes, int n_in,
                              void* d_out, int out_size) {
    const float* nodes = (const float*)d_in[0];
    const float* edges = (const float*)d_in[1];
    const int*   graph = (const int*)  d_in[2];
    const float* nnw   = (const float*)d_in[3];
    const float* nnb   = (const float*)d_in[4];
    const float* enw   = (const float*)d_in[5];
    const float* enb   = (const float*)d_in[6];
    const float* Wn1   = (const float*)d_in[7];
    const float* bn1   = (const float*)d_in[8];
    const float* Wn2   = (const float*)d_in[9];
    const float* bn2   = (const float*)d_in[10];
    const float* We1   = (const float*)d_in[11];
    const float* be1   = (const float*)d_in[12];
    const float* We2   = (const float*)d_in[13];
    const float* be2   = (const float*)d_in[14];

    float* out_nodes = (float*)d_out;
    float* out_edges = out_nodes + (long)N_NODES * D;

    static bool attr_done = false;
    cudaFuncSetAttribute(gemm1_tc<0, KN>, cudaFuncAttributeMaxDynamicSharedMemorySize, SMEMB);
    cudaFuncSetAttribute(gemm1_tc<1, KE>, cudaFuncAttributeMaxDynamicSharedMemorySize, SMEMB);
    cudaFuncSetAttribute(gemm2_tc,        cudaFuncAttributeMaxDynamicSharedMemorySize, SMEMB);
    (void)attr_done;

    // 1) msg = segment_sum(edges, dst)
    zero_msg_kernel<<<(N_NODES * D / 4 + 255) / 256, 256>>>();
    scatter_kernel<<<(int)(((long)N_EDGES * D + 255) / 256), 256>>>(edges, graph);

    // 2) node batchnorm stats -> fold into W1
    node_stats_partial<<<STAT_BLOCKS, KN>>>(nodes);
    stats_finalize<<<KN, STAT_BLOCKS>>>(KN, 1.f / N_NODES, nnw, nnb);
    fold_kernel<<<(HID + 255) / 256, 256>>>(KN, Wn1, bn1);
    w2cvt_kernel<<<(HID * D + 255) / 256, 256>>>(Wn2);

    // 3) node MLP
    {
        dim3 g1(HID / 128, (N_NODES + 127) / 128);
        gemm1_tc<0, KN><<<g1, 256, SMEMB>>>(nodes, nullptr, nullptr, nullptr, N_NODES);
        dim3 g2(1, (N_NODES + 127) / 128);
        gemm2_tc<<<g2, 256, SMEMB>>>(bn2, nodes, out_nodes, N_NODES);
    }

    // 4) edge batchnorm stats -> fold into W1
    edge_stats_partial<<<STAT_BLOCKS, KE>>>(out_nodes, edges, graph);
    stats_finalize<<<KE, STAT_BLOCKS>>>(KE, 1.f / N_EDGES, enw, enb);
    fold_kernel<<<(HID + 255) / 256, 256>>>(KE, We1, be1);
    w2cvt_kernel<<<(HID * D + 255) / 256, 256>>>(We2);

    // 5) edge MLP
    {
        dim3 g1(HID / 128, (N_EDGES + 127) / 128);
        gemm1_tc<1, KE><<<g1, 256, SMEMB>>>(nullptr, edges, graph, out_nodes, N_EDGES);
        dim3 g2(1, (N_EDGES + 127) / 128);
        gemm2_tc<<<g2, 256, SMEMB>>>(be2, edges, out_edges, N_EDGES);
    }
}

// round 7
// speedup vs baseline: 2.5885x; 1.2463x over previous
#include <cuda_runtime.h>
#include <cuda_fp16.h>
#include <math.h>
#include <stdint.h>

#define N_NODES 50000
#define N_EDGES 320000
#define D       128
#define HID     512
#define KN      256
#define KE      384
#define EPSV    1e-5f
#define STAT_BLOCKS 256

// ---------------- device scratch (allocation-free: static globals) ----------
__device__ float  g_msg[(size_t)N_NODES * D];           // 25.6 MB
__device__ __half g_H[(size_t)N_EDGES * HID];           // 327 MB hidden acts fp16
__device__ __half g_W1hT[(size_t)HID * KE];             // folded W1 transposed [n][k] fp16
__device__ __half g_W2h[(size_t)D * HID];               // W2 transposed [n][k] fp16
__device__ float  g_b1p[HID];
__device__ float  g_scale[KE];
__device__ float  g_shift[KE];
__device__ float  g_psum[(size_t)STAT_BLOCKS * KE];
__device__ float  g_psq [(size_t)STAT_BLOCKS * KE];

// ---------------- helpers ------------------------------------------------
__device__ __forceinline__ float gelu_exact(float x) {
    return 0.5f * x * (1.f + erff(x * 0.70710678118654752f));
}
__device__ __forceinline__ uint32_t smem_u32(const void* p) {
    uint32_t a;
    asm("{ .reg .u64 t; cvta.to.shared.u64 t, %1; cvt.u32.u64 %0, t; }" : "=r"(a) : "l"(p));
    return a;
}
__device__ __forceinline__ uint32_t pk2(float x, float y) {
    __half2 h = __floats2half2_rn(x, y);
    return *(uint32_t*)&h;
}
__device__ __forceinline__ void cp16s(uint32_t saddr, const void* g) {
    asm volatile("cp.async.cg.shared.global [%0], [%1], 16;" :: "r"(saddr), "l"(g));
}
#define CP_COMMIT() asm volatile("cp.async.commit_group;" ::: "memory")
#define CP_WAIT0()  asm volatile("cp.async.wait_group 0;" ::: "memory")

__device__ __forceinline__ void ldmx4(uint32_t* r, uint32_t addr) {
    asm volatile("ldmatrix.sync.aligned.m8n8.x4.shared.b16 {%0,%1,%2,%3}, [%4];"
        : "=r"(r[0]), "=r"(r[1]), "=r"(r[2]), "=r"(r[3]) : "r"(addr));
}
__device__ __forceinline__ void mma16(float* c, const uint32_t* a, const uint32_t* b) {
    asm volatile(
        "mma.sync.aligned.m16n8k16.row.col.f32.f16.f16.f32 "
        "{%0,%1,%2,%3}, {%4,%5,%6,%7}, {%8,%9}, {%0,%1,%2,%3};"
        : "+f"(c[0]), "+f"(c[1]), "+f"(c[2]), "+f"(c[3])
        : "r"(a[0]), "r"(a[1]), "r"(a[2]), "r"(a[3]), "r"(b[0]), "r"(b[1]));
}

// smem tile: 128 rows x 32 halves, row stride 80 bytes (64B data + 16B pad)
#define ROWB 80
#define TILEB (128 * ROWB)   // 10240 bytes

// ---------------- small kernels ----------------------------------------------
__global__ void zero_msg_kernel() {
    int i = blockIdx.x * blockDim.x + threadIdx.x;
    if (i < N_NODES * D / 4) ((float4*)g_msg)[i] = make_float4(0.f, 0.f, 0.f, 0.f);
}

__global__ void scatter_kernel(const float* __restrict__ edges,
                               const int* __restrict__ graph) {
    long idx = (long)blockIdx.x * blockDim.x + threadIdx.x;
    if (idx >= (long)N_EDGES * D) return;
    int e = (int)(idx >> 7);
    int c = (int)(idx & 127);
    int d = __ldg(&graph[N_EDGES + e]);
    atomicAdd(&g_msg[(long)d * D + c], edges[idx]);
}

__global__ void node_stats_partial(const float* __restrict__ nodes) {
    int col = threadIdx.x;
    float s = 0.f, q = 0.f;
    for (int r = blockIdx.x; r < N_NODES; r += gridDim.x) {
        float v = (col < D) ? nodes[(long)r * D + col]
                            : g_msg[(long)r * D + (col - D)];
        s += v; q += v * v;
    }
    g_psum[(long)blockIdx.x * KN + col] = s;
    g_psq [(long)blockIdx.x * KN + col] = q;
}

__global__ void edge_stats_partial(const float* __restrict__ nodesOut,
                                   const float* __restrict__ edges,
                                   const int* __restrict__ graph) {
    int col = threadIdx.x;
    float s = 0.f, q = 0.f;
    for (int r = blockIdx.x; r < N_EDGES; r += gridDim.x) {
        float v;
        if (col < D) {
            int si = __ldg(&graph[r]);
            v = nodesOut[(long)si * D + col];
        } else if (col < 2 * D) {
            int di = __ldg(&graph[N_EDGES + r]);
            v = nodesOut[(long)di * D + (col - D)];
        } else {
            v = edges[(long)r * D + (col - 2 * D)];
        }
        s += v; q += v * v;
    }
    g_psum[(long)blockIdx.x * KE + col] = s;
    g_psq [(long)blockIdx.x * KE + col] = q;
}

__global__ void stats_finalize(int ncols, float inv_count,
                               const float* __restrict__ w,
                               const float* __restrict__ b) {
    __shared__ float rs[STAT_BLOCKS], rq[STAT_BLOCKS];
    int col = blockIdx.x;
    int t = threadIdx.x;
    rs[t] = g_psum[(long)t * ncols + col];
    rq[t] = g_psq [(long)t * ncols + col];
    __syncthreads();
    for (int off = STAT_BLOCKS / 2; off > 0; off >>= 1) {
        if (t < off) { rs[t] += rs[t + off]; rq[t] += rq[t + off]; }
        __syncthreads();
    }
    if (t == 0) {
        float mean = rs[0] * inv_count;
        float var  = fmaxf(rq[0] * inv_count - mean * mean, 0.f);
        float sc   = rsqrtf(var + EPSV) * w[col];
        g_scale[col] = sc;
        g_shift[col] = b[col] - mean * sc;
    }
}

// fold BN into W1; write TRANSPOSED [n][k] fp16
__global__ void fold_kernel(int K, const float* __restrict__ W1,
                            const float* __restrict__ b1) {
    int j = blockIdx.x * blockDim.x + threadIdx.x;
    if (j >= HID) return;
    float acc = b1[j];
    for (int k = 0; k < K; k++) {
        float wv = W1[(long)k * HID + j];
        acc += g_shift[k] * wv;
        g_W1hT[(long)j * K + k] = __float2half_rn(wv * g_scale[k]);
    }
    g_b1p[j] = acc;
}

// W2 -> transposed [n][k] fp16
__global__ void w2cvt_kernel(const float* __restrict__ W2) {
    int i = blockIdx.x * blockDim.x + threadIdx.x;
    if (i >= D * HID) return;
    int n = i >> 9, k = i & 511;
    g_W2h[i] = __float2half_rn(W2[(long)k * D + n]);
}

// ---------------- warp-tile compute: 32(m) x 64(n) x 32(k) -------------------
// A smem [m][k] row-major; B smem [n][k] (k contiguous). Both use NON-trans
// ldmatrix: the mma B fragment wants consecutive-k pairs at fixed n, which is
// exactly what non-trans ldmatrix over n-rows yields.
__device__ __forceinline__ void compute_tile(float (&acc)[2][8][4],
                                             uint32_t sA, uint32_t sB,
                                             int wm, int wn, int lane) {
    #pragma unroll
    for (int kk = 0; kk < 32; kk += 16) {
        uint32_t a[2][4];
        #pragma unroll
        for (int mi = 0; mi < 2; mi++) {
            uint32_t addr = sA + (uint32_t)((wm + mi * 16 + (lane & 15)) * ROWB
                                            + kk * 2 + ((lane >> 4) & 1) * 16);
            ldmx4(a[mi], addr);
        }
        uint32_t b[4][4];
        #pragma unroll
        for (int nt = 0; nt < 4; nt++) {
            int nr = wn + nt * 16 + (lane & 7) + ((lane >> 4) & 1) * 8;
            int kof = kk + ((lane >> 3) & 1) * 8;
            ldmx4(b[nt], sB + (uint32_t)(nr * ROWB + kof * 2));
        }
        #pragma unroll
        for (int mi = 0; mi < 2; mi++)
            #pragma unroll
            for (int nt = 0; nt < 4; nt++) {
                mma16(acc[mi][nt * 2 + 0], a[mi], &b[nt][0]);
                mma16(acc[mi][nt * 2 + 1], a[mi], &b[nt][2]);
            }
    }
}

// ---------------- GEMM1: g_H = gelu(X @ W1 + b1), fp16 mma -------------------
// MODE 0: K=256, X[m] = [nodes[m], msg[m]]
// MODE 1: K=384, X[m] = [nodesOut[src[m]], nodesOut[dst[m]], edges[m]]
// CTA tile 128 x 128; grid.x = HID/128 = 4.
template <int MODE, int K>
__global__ __launch_bounds__(256)
void gemm1_hmma(const float* __restrict__ nodes,
                const float* __restrict__ edges,
                const int*   __restrict__ graph,
                const float* __restrict__ nodesOut,
                int M) {
    __shared__ __align__(16) char smem[4 * TILEB];
    __shared__ float sBias[128];
    uint32_t base = smem_u32(smem);
    uint32_t sA[2] = { base,             base + TILEB };
    uint32_t sB[2] = { base + 2 * TILEB, base + 3 * TILEB };

    const int tid = threadIdx.x, lane = tid & 31, wid = tid >> 5;
    const int wm = (wid & 3) * 32, wn = (wid >> 2) * 64;
    const int rowBase = blockIdx.y * 128;
    const int nBase = blockIdx.x * 128;
    const int S = K / 32;

    if (tid < 128) sBias[tid] = g_b1p[nBase + tid];

    const int r = tid >> 1, half = tid & 1;   // A fill: 2 threads/row
    const int mA = rowBase + r;
    const int mc = (mA < M) ? mA : (M - 1);
    int vsrc = 0, vdst = 0;
    if (MODE == 1) { vsrc = graph[mc]; vdst = graph[N_EDGES + mc]; }
    const int nrB = tid >> 1;                 // B fill: 2 threads/row

    float acc[2][8][4];
    #pragma unroll
    for (int i = 0; i < 2; i++)
        #pragma unroll
        for (int j = 0; j < 8; j++)
            #pragma unroll
            for (int c = 0; c < 4; c++) acc[i][j][c] = 0.f;

    auto fill = [&](int s, int buf) {
        // A: LDG fp32 -> fp16 -> STS (16 floats per thread)
        int khalf = s * 32 + half * 16;
        int seg = khalf >> 7, l = khalf & 127;
        const float* p;
        if (MODE == 0) {
            p = (seg == 0 ? nodes + (long)mc * D : g_msg + (long)mc * D) + l;
        } else {
            p = (seg == 0 ? nodesOut + (long)vsrc * D
               : seg == 1 ? nodesOut + (long)vdst * D
                          : edges + (long)mc * D) + l;
        }
        uint32_t h[8];
        #pragma unroll
        for (int q = 0; q < 4; q++) {
            float4 v = *(const float4*)(p + 4 * q);
            h[q * 2 + 0] = pk2(v.x, v.y);
            h[q * 2 + 1] = pk2(v.z, v.w);
        }
        uint32_t dA = sA[buf] + (uint32_t)(r * ROWB + half * 32);
        asm volatile("st.shared.v4.b32 [%0], {%1,%2,%3,%4};"
                     :: "r"(dA), "r"(h[0]), "r"(h[1]), "r"(h[2]), "r"(h[3]));
        asm volatile("st.shared.v4.b32 [%0], {%1,%2,%3,%4};"
                     :: "r"(dA + 16), "r"(h[4]), "r"(h[5]), "r"(h[6]), "r"(h[7]));
        // B: cp.async 32B per thread from g_W1hT
        const __half* src = g_W1hT + (long)(nBase + nrB) * K + s * 32 + half * 16;
        uint32_t dB = sB[buf] + (uint32_t)(nrB * ROWB + half * 32);
        cp16s(dB,      src);
        cp16s(dB + 16, src + 8);
        CP_COMMIT();
    };

    fill(0, 0);
    for (int s = 0; s < S; s++) {
        int buf = s & 1;
        CP_WAIT0();
        __syncthreads();
        if (s + 1 < S) fill(s + 1, buf ^ 1);
        compute_tile(acc, sA[buf], sB[buf], wm, wn, lane);
    }

    // epilogue: bias + exact gelu -> fp16 g_H
    const int g = lane >> 2, tg = lane & 3;
    #pragma unroll
    for (int mi = 0; mi < 2; mi++) {
        int row0 = rowBase + wm + mi * 16 + g;
        #pragma unroll
        for (int ni = 0; ni < 8; ni++) {
            int c0 = wn + ni * 8 + tg * 2;
            int col = nBase + c0;
            float b0 = sBias[c0], b1 = sBias[c0 + 1];
            if (row0 < M) {
                __half2 hv = __floats2half2_rn(gelu_exact(acc[mi][ni][0] + b0),
                                               gelu_exact(acc[mi][ni][1] + b1));
                *(__half2*)(g_H + (size_t)row0 * HID + col) = hv;
            }
            if (row0 + 8 < M) {
                __half2 hv = __floats2half2_rn(gelu_exact(acc[mi][ni][2] + b0),
                                               gelu_exact(acc[mi][ni][3] + b1));
                *(__half2*)(g_H + (size_t)(row0 + 8) * HID + col) = hv;
            }
        }
    }
}

// ---------------- GEMM2: out = g_H @ W2 + b2 + res, fp16 mma -----------------
__global__ __launch_bounds__(256)
void gemm2_hmma(const float* __restrict__ b2,
                const float* __restrict__ res,
                float* __restrict__ out,
                int M) {
    __shared__ __align__(16) char smem[4 * TILEB];
    __shared__ float sBias[128];
    uint32_t base = smem_u32(smem);
    uint32_t sA[2] = { base,             base + TILEB };
    uint32_t sB[2] = { base + 2 * TILEB, base + 3 * TILEB };

    const int tid = threadIdx.x, lane = tid & 31, wid = tid >> 5;
    const int wm = (wid & 3) * 32, wn = (wid >> 2) * 64;
    const int rowBase = blockIdx.y * 128;
    const int S = HID / 32;   // 16

    if (tid < 128) sBias[tid] = b2[tid];

    const int r = tid >> 1, half = tid & 1;
    const int mA = rowBase + r;
    const int mc = (mA < M) ? mA : (M - 1);

    float acc[2][8][4];
    #pragma unroll
    for (int i = 0; i < 2; i++)
        #pragma unroll
        for (int j = 0; j < 8; j++)
            #pragma unroll
            for (int c = 0; c < 4; c++) acc[i][j][c] = 0.f;

    auto fill = [&](int s, int buf) {
        const __half* srcA = g_H + (size_t)mc * HID + s * 32 + half * 16;
        uint32_t dA = sA[buf] + (uint32_t)(r * ROWB + half * 32);
        cp16s(dA,      srcA);
        cp16s(dA + 16, srcA + 8);
        const __half* srcB = g_W2h + (long)r * HID + s * 32 + half * 16;
        uint32_t dB = sB[buf] + (uint32_t)(r * ROWB + half * 32);
        cp16s(dB,      srcB);
        cp16s(dB + 16, srcB + 8);
        CP_COMMIT();
    };

    fill(0, 0);
    for (int s = 0; s < S; s++) {
        int buf = s & 1;
        CP_WAIT0();
        __syncthreads();
        if (s + 1 < S) fill(s + 1, buf ^ 1);
        compute_tile(acc, sA[buf], sB[buf], wm, wn, lane);
    }

    const int g = lane >> 2, tg = lane & 3;
    #pragma unroll
    for (int mi = 0; mi < 2; mi++) {
        int row0 = rowBase + wm + mi * 16 + g;
        #pragma unroll
        for (int ni = 0; ni < 8; ni++) {
            int col = wn + ni * 8 + tg * 2;
            float b0 = sBias[col], b1 = sBias[col + 1];
            if (row0 < M) {
                long o = (long)row0 * D + col;
                out[o]     = acc[mi][ni][0] + b0 + res[o];
                out[o + 1] = acc[mi][ni][1] + b1 + res[o + 1];
            }
            if (row0 + 8 < M) {
                long o = (long)(row0 + 8) * D + col;
                out[o]     = acc[mi][ni][2] + b0 + res[o];
                out[o + 1] = acc[mi][ni][3] + b1 + res[o + 1];
            }
        }
    }
}

// ---------------- launch -----------------------------------------------------
extern "C" void kernel_launch(void* const* d_in, const int* in_sizes, int n_in,
                              void* d_out, int out_size) {
    const float* nodes = (const float*)d_in[0];
    const float* edges = (const float*)d_in[1];
    const int*   graph = (const int*)  d_in[2];
    const float* nnw   = (const float*)d_in[3];
    const float* nnb   = (const float*)d_in[4];
    const float* enw   = (const float*)d_in[5];
    const float* enb   = (const float*)d_in[6];
    const float* Wn1   = (const float*)d_in[7];
    const float* bn1   = (const float*)d_in[8];
    const float* Wn2   = (const float*)d_in[9];
    const float* bn2   = (const float*)d_in[10];
    const float* We1   = (const float*)d_in[11];
    const float* be1   = (const float*)d_in[12];
    const float* We2   = (const float*)d_in[13];
    const float* be2   = (const float*)d_in[14];

    float* out_nodes = (float*)d_out;
    float* out_edges = out_nodes + (long)N_NODES * D;

    // 1) msg = segment_sum(edges, dst)
    zero_msg_kernel<<<(N_NODES * D / 4 + 255) / 256, 256>>>();
    scatter_kernel<<<(int)(((long)N_EDGES * D + 255) / 256), 256>>>(edges, graph);

    // 2) node batchnorm stats -> fold into W1
    node_stats_partial<<<STAT_BLOCKS, KN>>>(nodes);
    stats_finalize<<<KN, STAT_BLOCKS>>>(KN, 1.f / N_NODES, nnw, nnb);
    fold_kernel<<<(HID + 255) / 256, 256>>>(KN, Wn1, bn1);
    w2cvt_kernel<<<(D * HID + 255) / 256, 256>>>(Wn2);

    // 3) node MLP
    {
        dim3 g1(HID / 128, (N_NODES + 127) / 128);
        gemm1_hmma<0, KN><<<g1, 256>>>(nodes, nullptr, nullptr, nullptr, N_NODES);
        dim3 g2(1, (N_NODES + 127) / 128);
        gemm2_hmma<<<g2, 256>>>(bn2, nodes, out_nodes, N_NODES);
    }

    // 4) edge batchnorm stats -> fold into W1
    edge_stats_partial<<<STAT_BLOCKS, KE>>>(out_nodes, edges, graph);
    stats_finalize<<<KE, STAT_BLOCKS>>>(KE, 1.f / N_EDGES, enw, enb);
    fold_kernel<<<(HID + 255) / 256, 256>>>(KE, We1, be1);
    w2cvt_kernel<<<(D * HID + 255) / 256, 256>>>(We2);

    // 5) edge MLP
    {
        dim3 g1(HID / 128, (N_EDGES + 127) / 128);
        gemm1_hmma<1, KE><<<g1, 256>>>(nullptr, edges, graph, out_nodes, N_EDGES);
        dim3 g2(1, (N_EDGES + 127) / 128);
        gemm2_hmma<<<g2, 256>>>(be2, edges, out_edges, N_EDGES);
    }
}

// round 8
// speedup vs baseline: 2.8694x; 1.1085x over previous
#include <cuda_runtime.h>
#include <cuda_fp16.h>
#include <math.h>
#include <stdint.h>

#define N_NODES 50000
#define N_EDGES 320000
#define D       128
#define HID     512
#define KN      256
#define KE      384
#define EPSV    1e-5f
#define STAT_BLOCKS 256

// ---------------- device scratch (allocation-free: static globals) ----------
__device__ float  g_msg[(size_t)N_NODES * D];           // 25.6 MB
__device__ __half g_H[(size_t)N_EDGES * HID];           // 327 MB hidden acts fp16
__device__ __half g_W1hT[(size_t)HID * KE];             // folded W1 transposed [n][k] fp16
__device__ __half g_W2h[(size_t)D * HID];               // W2 transposed [n][k] fp16
__device__ float  g_b1p[HID];
__device__ float  g_scale[KE];
__device__ float  g_shift[KE];
__device__ float  g_psum[(size_t)STAT_BLOCKS * KE];
__device__ float  g_psq [(size_t)STAT_BLOCKS * KE];

// ---------------- helpers ------------------------------------------------
__device__ __forceinline__ float gelu_exact(float x) {
    return 0.5f * x * (1.f + erff(x * 0.70710678118654752f));
}
__device__ __forceinline__ uint32_t smem_u32(const void* p) {
    uint32_t a;
    asm("{ .reg .u64 t; cvta.to.shared.u64 t, %1; cvt.u32.u64 %0, t; }" : "=r"(a) : "l"(p));
    return a;
}
__device__ __forceinline__ uint32_t pk2(float x, float y) {
    __half2 h = __floats2half2_rn(x, y);
    return *(uint32_t*)&h;
}
__device__ __forceinline__ void cp16s(uint32_t saddr, const void* g) {
    asm volatile("cp.async.cg.shared.global [%0], [%1], 16;" :: "r"(saddr), "l"(g));
}
#define CP_COMMIT() asm volatile("cp.async.commit_group;" ::: "memory")
#define CP_WAIT0()  asm volatile("cp.async.wait_group 0;" ::: "memory")

__device__ __forceinline__ void ldmx4(uint32_t* r, uint32_t addr) {
    asm volatile("ldmatrix.sync.aligned.m8n8.x4.shared.b16 {%0,%1,%2,%3}, [%4];"
        : "=r"(r[0]), "=r"(r[1]), "=r"(r[2]), "=r"(r[3]) : "r"(addr));
}
__device__ __forceinline__ void mma16(float* c, const uint32_t* a, const uint32_t* b) {
    asm volatile(
        "mma.sync.aligned.m16n8k16.row.col.f32.f16.f16.f32 "
        "{%0,%1,%2,%3}, {%4,%5,%6,%7}, {%8,%9}, {%0,%1,%2,%3};"
        : "+f"(c[0]), "+f"(c[1]), "+f"(c[2]), "+f"(c[3])
        : "r"(a[0]), "r"(a[1]), "r"(a[2]), "r"(a[3]), "r"(b[0]), "r"(b[1]));
}

// smem tile: 128 rows x 32 halves, row stride 80 bytes (64B data + 16B pad)
#define ROWB 80
#define TILEB (128 * ROWB)   // 10240 bytes

// ---------------- small kernels ----------------------------------------------
__global__ void zero_msg_kernel() {
    int i = blockIdx.x * blockDim.x + threadIdx.x;
    if (i < N_NODES * D / 4) ((float4*)g_msg)[i] = make_float4(0.f, 0.f, 0.f, 0.f);
}

__global__ void scatter_kernel(const float* __restrict__ edges,
                               const int* __restrict__ graph) {
    long idx = (long)blockIdx.x * blockDim.x + threadIdx.x;
    if (idx >= (long)N_EDGES * D) return;
    int e = (int)(idx >> 7);
    int c = (int)(idx & 127);
    int d = __ldg(&graph[N_EDGES + e]);
    atomicAdd(&g_msg[(long)d * D + c], edges[idx]);
}

__global__ void node_stats_partial(const float* __restrict__ nodes) {
    int col = threadIdx.x;
    float s = 0.f, q = 0.f;
    for (int r = blockIdx.x; r < N_NODES; r += gridDim.x) {
        float v = (col < D) ? nodes[(long)r * D + col]
                            : g_msg[(long)r * D + (col - D)];
        s += v; q += v * v;
    }
    g_psum[(long)blockIdx.x * KN + col] = s;
    g_psq [(long)blockIdx.x * KN + col] = q;
}

__global__ void edge_stats_partial(const float* __restrict__ nodesOut,
                                   const float* __restrict__ edges,
                                   const int* __restrict__ graph) {
    int col = threadIdx.x;
    float s = 0.f, q = 0.f;
    for (int r = blockIdx.x; r < N_EDGES; r += gridDim.x) {
        float v;
        if (col < D) {
            int si = __ldg(&graph[r]);
            v = nodesOut[(long)si * D + col];
        } else if (col < 2 * D) {
            int di = __ldg(&graph[N_EDGES + r]);
            v = nodesOut[(long)di * D + (col - D)];
        } else {
            v = edges[(long)r * D + (col - 2 * D)];
        }
        s += v; q += v * v;
    }
    g_psum[(long)blockIdx.x * KE + col] = s;
    g_psq [(long)blockIdx.x * KE + col] = q;
}

__global__ void stats_finalize(int ncols, float inv_count,
                               const float* __restrict__ w,
                               const float* __restrict__ b) {
    __shared__ float rs[STAT_BLOCKS], rq[STAT_BLOCKS];
    int col = blockIdx.x;
    int t = threadIdx.x;
    rs[t] = g_psum[(long)t * ncols + col];
    rq[t] = g_psq [(long)t * ncols + col];
    __syncthreads();
    for (int off = STAT_BLOCKS / 2; off > 0; off >>= 1) {
        if (t < off) { rs[t] += rs[t + off]; rq[t] += rq[t + off]; }
        __syncthreads();
    }
    if (t == 0) {
        float mean = rs[0] * inv_count;
        float var  = fmaxf(rq[0] * inv_count - mean * mean, 0.f);
        float sc   = rsqrtf(var + EPSV) * w[col];
        g_scale[col] = sc;
        g_shift[col] = b[col] - mean * sc;
    }
}

// fold BN into W1; write TRANSPOSED [n][k] fp16
__global__ void fold_kernel(int K, const float* __restrict__ W1,
                            const float* __restrict__ b1) {
    int j = blockIdx.x * blockDim.x + threadIdx.x;
    if (j >= HID) return;
    float acc = b1[j];
    for (int k = 0; k < K; k++) {
        float wv = W1[(long)k * HID + j];
        acc += g_shift[k] * wv;
        g_W1hT[(long)j * K + k] = __float2half_rn(wv * g_scale[k]);
    }
    g_b1p[j] = acc;
}

// W2 -> transposed [n][k] fp16
__global__ void w2cvt_kernel(const float* __restrict__ W2) {
    int i = blockIdx.x * blockDim.x + threadIdx.x;
    if (i >= D * HID) return;
    int n = i >> 9, k = i & 511;
    g_W2h[i] = __float2half_rn(W2[(long)k * D + n]);
}

// ---------------- warp-tile compute: 32(m) x 64(n) x 32(k) -------------------
// A smem [m][k] row-major; B smem [n][k] (k contiguous). Both NON-trans
// ldmatrix (mma B fragment = consecutive-k pairs at fixed n).
__device__ __forceinline__ void compute_tile(float (&acc)[2][8][4],
                                             uint32_t sA, uint32_t sB,
                                             int wm, int wn, int lane) {
    #pragma unroll
    for (int kk = 0; kk < 32; kk += 16) {
        uint32_t a[2][4];
        #pragma unroll
        for (int mi = 0; mi < 2; mi++) {
            uint32_t addr = sA + (uint32_t)((wm + mi * 16 + (lane & 15)) * ROWB
                                            + kk * 2 + ((lane >> 4) & 1) * 16);
            ldmx4(a[mi], addr);
        }
        uint32_t b[4][4];
        #pragma unroll
        for (int nt = 0; nt < 4; nt++) {
            int nr = wn + nt * 16 + (lane & 7) + ((lane >> 4) & 1) * 8;
            int kof = kk + ((lane >> 3) & 1) * 8;
            ldmx4(b[nt], sB + (uint32_t)(nr * ROWB + kof * 2));
        }
        #pragma unroll
        for (int mi = 0; mi < 2; mi++)
            #pragma unroll
            for (int nt = 0; nt < 4; nt++) {
                mma16(acc[mi][nt * 2 + 0], a[mi], &b[nt][0]);
                mma16(acc[mi][nt * 2 + 1], a[mi], &b[nt][2]);
            }
    }
}

// ---------------- GEMM1: g_H = gelu(X @ W1 + b1), fp16 mma -------------------
// MODE 0: K=256, X[m] = [nodes[m], msg[m]]
// MODE 1: K=384, X[m] = [nodesOut[src[m]], nodesOut[dst[m]], edges[m]]
// A operand is register-prefetched: LDGs for chunk s+1 issue before compute(s).
template <int MODE, int K>
__global__ __launch_bounds__(256, 2)
void gemm1_hmma(const float* __restrict__ nodes,
                const float* __restrict__ edges,
                const int*   __restrict__ graph,
                const float* __restrict__ nodesOut,
                int M) {
    __shared__ __align__(16) char smem[4 * TILEB];
    __shared__ float sBias[128];
    uint32_t base = smem_u32(smem);
    uint32_t sA[2] = { base,             base + TILEB };
    uint32_t sB[2] = { base + 2 * TILEB, base + 3 * TILEB };

    const int tid = threadIdx.x, lane = tid & 31, wid = tid >> 5;
    const int wm = (wid & 3) * 32, wn = (wid >> 2) * 64;
    const int rowBase = blockIdx.y * 128;
    const int nBase = blockIdx.x * 128;
    const int S = K / 32;

    if (tid < 128) sBias[tid] = g_b1p[nBase + tid];

    const int r = tid >> 1, half = tid & 1;   // A fill: 2 threads/row, 16 floats each
    const int mA = rowBase + r;
    const int mc = (mA < M) ? mA : (M - 1);
    int vsrc = 0, vdst = 0;
    if (MODE == 1) { vsrc = graph[mc]; vdst = graph[N_EDGES + mc]; }
    const int nrB = tid >> 1;                 // B fill: 2 threads/row

    float acc[2][8][4];
    #pragma unroll
    for (int i = 0; i < 2; i++)
        #pragma unroll
        for (int j = 0; j < 8; j++)
            #pragma unroll
            for (int c = 0; c < 4; c++) acc[i][j][c] = 0.f;

    float4 av[4];   // A prefetch registers (16 fp32)

    auto ldA = [&](int s) {
        int khalf = s * 32 + half * 16;
        int seg = khalf >> 7, l = khalf & 127;
        const float* p;
        if (MODE == 0) {
            p = (seg == 0 ? nodes + (long)mc * D : g_msg + (long)mc * D) + l;
        } else {
            p = (seg == 0 ? nodesOut + (long)vsrc * D
               : seg == 1 ? nodesOut + (long)vdst * D
                          : edges + (long)mc * D) + l;
        }
        #pragma unroll
        for (int q = 0; q < 4; q++) av[q] = *(const float4*)(p + 4 * q);
    };
    auto stsA = [&](int buf) {
        uint32_t h[8];
        #pragma unroll
        for (int q = 0; q < 4; q++) {
            h[q * 2 + 0] = pk2(av[q].x, av[q].y);
            h[q * 2 + 1] = pk2(av[q].z, av[q].w);
        }
        uint32_t dA = sA[buf] + (uint32_t)(r * ROWB + half * 32);
        asm volatile("st.shared.v4.b32 [%0], {%1,%2,%3,%4};"
                     :: "r"(dA), "r"(h[0]), "r"(h[1]), "r"(h[2]), "r"(h[3]));
        asm volatile("st.shared.v4.b32 [%0], {%1,%2,%3,%4};"
                     :: "r"(dA + 16), "r"(h[4]), "r"(h[5]), "r"(h[6]), "r"(h[7]));
    };
    auto issueB = [&](int s, int buf) {
        const __half* src = g_W1hT + (long)(nBase + nrB) * K + s * 32 + half * 16;
        uint32_t dB = sB[buf] + (uint32_t)(nrB * ROWB + half * 32);
        cp16s(dB,      src);
        cp16s(dB + 16, src + 8);
        CP_COMMIT();
    };

    ldA(0);
    issueB(0, 0);
    for (int s = 0; s < S; s++) {
        int buf = s & 1;
        stsA(buf);                 // A LDGs landed long ago; pack + store
        CP_WAIT0();
        __syncthreads();
        if (s + 1 < S) { issueB(s + 1, buf ^ 1); ldA(s + 1); }  // in flight during compute
        compute_tile(acc, sA[buf], sB[buf], wm, wn, lane);
    }

    // epilogue: bias + exact gelu -> fp16 g_H
    const int g = lane >> 2, tg = lane & 3;
    #pragma unroll
    for (int mi = 0; mi < 2; mi++) {
        int row0 = rowBase + wm + mi * 16 + g;
        #pragma unroll
        for (int ni = 0; ni < 8; ni++) {
            int c0 = wn + ni * 8 + tg * 2;
            int col = nBase + c0;
            float b0 = sBias[c0], b1 = sBias[c0 + 1];
            if (row0 < M) {
                __half2 hv = __floats2half2_rn(gelu_exact(acc[mi][ni][0] + b0),
                                               gelu_exact(acc[mi][ni][1] + b1));
                *(__half2*)(g_H + (size_t)row0 * HID + col) = hv;
            }
            if (row0 + 8 < M) {
                __half2 hv = __floats2half2_rn(gelu_exact(acc[mi][ni][2] + b0),
                                               gelu_exact(acc[mi][ni][3] + b1));
                *(__half2*)(g_H + (size_t)(row0 + 8) * HID + col) = hv;
            }
        }
    }
}

// ---------------- GEMM2: out = g_H @ W2 + b2 + res, fp16 mma -----------------
__global__ __launch_bounds__(256, 2)
void gemm2_hmma(const float* __restrict__ b2,
                const float* __restrict__ res,
                float* __restrict__ out,
                int M) {
    __shared__ __align__(16) char smem[4 * TILEB];
    __shared__ float sBias[128];
    uint32_t base = smem_u32(smem);
    uint32_t sA[2] = { base,             base + TILEB };
    uint32_t sB[2] = { base + 2 * TILEB, base + 3 * TILEB };

    const int tid = threadIdx.x, lane = tid & 31, wid = tid >> 5;
    const int wm = (wid & 3) * 32, wn = (wid >> 2) * 64;
    const int rowBase = blockIdx.y * 128;
    const int S = HID / 32;   // 16

    if (tid < 128) sBias[tid] = b2[tid];

    const int r = tid >> 1, half = tid & 1;
    const int mA = rowBase + r;
    const int mc = (mA < M) ? mA : (M - 1);

    float acc[2][8][4];
    #pragma unroll
    for (int i = 0; i < 2; i++)
        #pragma unroll
        for (int j = 0; j < 8; j++)
            #pragma unroll
            for (int c = 0; c < 4; c++) acc[i][j][c] = 0.f;

    auto fill = [&](int s, int buf) {
        const __half* srcA = g_H + (size_t)mc * HID + s * 32 + half * 16;
        uint32_t dA = sA[buf] + (uint32_t)(r * ROWB + half * 32);
        cp16s(dA,      srcA);
        cp16s(dA + 16, srcA + 8);
        const __half* srcB = g_W2h + (long)r * HID + s * 32 + half * 16;
        uint32_t dB = sB[buf] + (uint32_t)(r * ROWB + half * 32);
        cp16s(dB,      srcB);
        cp16s(dB + 16, srcB + 8);
        CP_COMMIT();
    };

    fill(0, 0);
    for (int s = 0; s < S; s++) {
        int buf = s & 1;
        CP_WAIT0();
        __syncthreads();
        if (s + 1 < S) fill(s + 1, buf ^ 1);
        compute_tile(acc, sA[buf], sB[buf], wm, wn, lane);
    }

    const int g = lane >> 2, tg = lane & 3;
    #pragma unroll
    for (int mi = 0; mi < 2; mi++) {
        int row0 = rowBase + wm + mi * 16 + g;
        #pragma unroll
        for (int ni = 0; ni < 8; ni++) {
            int col = wn + ni * 8 + tg * 2;
            float b0 = sBias[col], b1 = sBias[col + 1];
            if (row0 < M) {
                long o = (long)row0 * D + col;
                out[o]     = acc[mi][ni][0] + b0 + res[o];
                out[o + 1] = acc[mi][ni][1] + b1 + res[o + 1];
            }
            if (row0 + 8 < M) {
                long o = (long)(row0 + 8) * D + col;
                out[o]     = acc[mi][ni][2] + b0 + res[o];
                out[o + 1] = acc[mi][ni][3] + b1 + res[o + 1];
            }
        }
    }
}

// ---------------- launch -----------------------------------------------------
extern "C" void kernel_launch(void* const* d_in, const int* in_sizes, int n_in,
                              void* d_out, int out_size) {
    const float* nodes = (const float*)d_in[0];
    const float* edges = (const float*)d_in[1];
    const int*   graph = (const int*)  d_in[2];
    const float* nnw   = (const float*)d_in[3];
    const float* nnb   = (const float*)d_in[4];
    const float* enw   = (const float*)d_in[5];
    const float* enb   = (const float*)d_in[6];
    const float* Wn1   = (const float*)d_in[7];
    const float* bn1   = (const float*)d_in[8];
    const float* Wn2   = (const float*)d_in[9];
    const float* bn2   = (const float*)d_in[10];
    const float* We1   = (const float*)d_in[11];
    const float* be1   = (const float*)d_in[12];
    const float* We2   = (const float*)d_in[13];
    const float* be2   = (const float*)d_in[14];

    float* out_nodes = (float*)d_out;
    float* out_edges = out_nodes + (long)N_NODES * D;

    // 1) msg = segment_sum(edges, dst)
    zero_msg_kernel<<<(N_NODES * D / 4 + 255) / 256, 256>>>();
    scatter_kernel<<<(int)(((long)N_EDGES * D + 255) / 256), 256>>>(edges, graph);

    // 2) node batchnorm stats -> fold into W1
    node_stats_partial<<<STAT_BLOCKS, KN>>>(nodes);
    stats_finalize<<<KN, STAT_BLOCKS>>>(KN, 1.f / N_NODES, nnw, nnb);
    fold_kernel<<<(HID + 255) / 256, 256>>>(KN, Wn1, bn1);
    w2cvt_kernel<<<(D * HID + 255) / 256, 256>>>(Wn2);

    // 3) node MLP
    {
        dim3 g1(HID / 128, (N_NODES + 127) / 128);
        gemm1_hmma<0, KN><<<g1, 256>>>(nodes, nullptr, nullptr, nullptr, N_NODES);
        dim3 g2(1, (N_NODES + 127) / 128);
        gemm2_hmma<<<g2, 256>>>(bn2, nodes, out_nodes, N_NODES);
    }

    // 4) edge batchnorm stats -> fold into W1
    edge_stats_partial<<<STAT_BLOCKS, KE>>>(out_nodes, edges, graph);
    stats_finalize<<<KE, STAT_BLOCKS>>>(KE, 1.f / N_EDGES, enw, enb);
    fold_kernel<<<(HID + 255) / 256, 256>>>(KE, We1, be1);
    w2cvt_kernel<<<(D * HID + 255) / 256, 256>>>(We2);

    // 5) edge MLP
    {
        dim3 g1(HID / 128, (N_EDGES + 127) / 128);
        gemm1_hmma<1, KE><<<g1, 256>>>(nullptr, edges, graph, out_nodes, N_EDGES);
        dim3 g2(1, (N_EDGES + 127) / 128);
        gemm2_hmma<<<g2, 256>>>(be2, edges, out_edges, N_EDGES);
    }
}

// round 9
// speedup vs baseline: 2.9109x; 1.0145x over previous
#include <cuda_runtime.h>
#include <cuda_fp16.h>
#include <math.h>
#include <stdint.h>

#define N_NODES 50000
#define N_EDGES 320000
#define D       128
#define HID     512
#define KN      256
#define KE      384
#define EPSV    1e-5f
#define STAT_BLOCKS 256

// ---------------- device scratch (allocation-free: static globals) ----------
__device__ float  g_msg[(size_t)N_NODES * D];           // fp32 scatter target
__device__ __half g_H[(size_t)N_EDGES * HID];           // hidden acts fp16
__device__ __half g_W1hT[(size_t)HID * KE];             // folded W1 [n][k] fp16
__device__ __half g_W2h[(size_t)D * HID];               // W2 [n][k] fp16
__device__ __half g_nodes_h[(size_t)N_NODES * D];       // fp16 mirrors
__device__ __half g_msg_h[(size_t)N_NODES * D];
__device__ __half g_no_h[(size_t)N_NODES * D];          // out_nodes fp16
__device__ __half g_edges_h[(size_t)N_EDGES * D];
__device__ float  g_b1p[HID];
__device__ float  g_scale[KE];
__device__ float  g_shift[KE];
__device__ float  g_psum[(size_t)STAT_BLOCKS * KE];
__device__ float  g_psq [(size_t)STAT_BLOCKS * KE];

// ---------------- helpers ------------------------------------------------
__device__ __forceinline__ float gelu_exact(float x) {
    return 0.5f * x * (1.f + erff(x * 0.70710678118654752f));
}
__device__ __forceinline__ uint32_t smem_u32(const void* p) {
    uint32_t a;
    asm("{ .reg .u64 t; cvta.to.shared.u64 t, %1; cvt.u32.u64 %0, t; }" : "=r"(a) : "l"(p));
    return a;
}
__device__ __forceinline__ void cp16s(uint32_t saddr, const void* g) {
    asm volatile("cp.async.cg.shared.global [%0], [%1], 16;" :: "r"(saddr), "l"(g));
}
#define CP_COMMIT() asm volatile("cp.async.commit_group;" ::: "memory")
#define CP_WAIT0()  asm volatile("cp.async.wait_group 0;" ::: "memory")

__device__ __forceinline__ void ldmx4(uint32_t* r, uint32_t addr) {
    asm volatile("ldmatrix.sync.aligned.m8n8.x4.shared.b16 {%0,%1,%2,%3}, [%4];"
        : "=r"(r[0]), "=r"(r[1]), "=r"(r[2]), "=r"(r[3]) : "r"(addr));
}
__device__ __forceinline__ void mma16(float* c, const uint32_t* a, const uint32_t* b) {
    asm volatile(
        "mma.sync.aligned.m16n8k16.row.col.f32.f16.f16.f32 "
        "{%0,%1,%2,%3}, {%4,%5,%6,%7}, {%8,%9}, {%0,%1,%2,%3};"
        : "+f"(c[0]), "+f"(c[1]), "+f"(c[2]), "+f"(c[3])
        : "r"(a[0]), "r"(a[1]), "r"(a[2]), "r"(a[3]), "r"(b[0]), "r"(b[1]));
}

// smem tile rows: 64 halves = 128B data + 16B pad = 144B stride
#define ROWB 144
#define ATILE (128 * ROWB)    // 18432 B
#define BTILE1 (256 * ROWB)   // 36864 B (gemm1 B: 256 n-rows)
#define BTILE2 (128 * ROWB)   // 18432 B (gemm2 B: 128 n-rows)

// ---------------- small kernels ----------------------------------------------
__global__ void zero_msg_kernel() {
    int i = blockIdx.x * blockDim.x + threadIdx.x;
    if (i < N_NODES * D / 4) ((float4*)g_msg)[i] = make_float4(0.f, 0.f, 0.f, 0.f);
}

__global__ void scatter_kernel(const float* __restrict__ edges,
                               const int* __restrict__ graph) {
    long idx = (long)blockIdx.x * blockDim.x + threadIdx.x;
    if (idx >= (long)N_EDGES * D) return;
    int e = (int)(idx >> 7);
    int c = (int)(idx & 127);
    int d = __ldg(&graph[N_EDGES + e]);
    atomicAdd(&g_msg[(long)d * D + c], edges[idx]);
}

// fp32 -> fp16 stream convert (n multiple of 4)
__global__ void cvt_h_kernel(const float* __restrict__ src, __half* __restrict__ dst, long n) {
    long i = ((long)blockIdx.x * blockDim.x + threadIdx.x) * 4;
    if (i >= n) return;
    float4 v = *(const float4*)(src + i);
    __half2 h0 = __floats2half2_rn(v.x, v.y);
    __half2 h1 = __floats2half2_rn(v.z, v.w);
    *(uint2*)(dst + i) = make_uint2(*(uint32_t*)&h0, *(uint32_t*)&h1);
}

__global__ void node_stats_partial(const float* __restrict__ nodes) {
    int col = threadIdx.x;
    float s = 0.f, q = 0.f;
    for (int r = blockIdx.x; r < N_NODES; r += gridDim.x) {
        float v = (col < D) ? nodes[(long)r * D + col]
                            : g_msg[(long)r * D + (col - D)];
        s += v; q += v * v;
    }
    g_psum[(long)blockIdx.x * KN + col] = s;
    g_psq [(long)blockIdx.x * KN + col] = q;
}

__global__ void edge_stats_partial(const float* __restrict__ nodesOut,
                                   const float* __restrict__ edges,
                                   const int* __restrict__ graph) {
    int col = threadIdx.x;
    float s = 0.f, q = 0.f;
    for (int r = blockIdx.x; r < N_EDGES; r += gridDim.x) {
        float v;
        if (col < D) {
            int si = __ldg(&graph[r]);
            v = nodesOut[(long)si * D + col];
        } else if (col < 2 * D) {
            int di = __ldg(&graph[N_EDGES + r]);
            v = nodesOut[(long)di * D + (col - D)];
        } else {
            v = edges[(long)r * D + (col - 2 * D)];
        }
        s += v; q += v * v;
    }
    g_psum[(long)blockIdx.x * KE + col] = s;
    g_psq [(long)blockIdx.x * KE + col] = q;
}

__global__ void stats_finalize(int ncols, float inv_count,
                               const float* __restrict__ w,
                               const float* __restrict__ b) {
    __shared__ float rs[STAT_BLOCKS], rq[STAT_BLOCKS];
    int col = blockIdx.x;
    int t = threadIdx.x;
    rs[t] = g_psum[(long)t * ncols + col];
    rq[t] = g_psq [(long)t * ncols + col];
    __syncthreads();
    for (int off = STAT_BLOCKS / 2; off > 0; off >>= 1) {
        if (t < off) { rs[t] += rs[t + off]; rq[t] += rq[t + off]; }
        __syncthreads();
    }
    if (t == 0) {
        float mean = rs[0] * inv_count;
        float var  = fmaxf(rq[0] * inv_count - mean * mean, 0.f);
        float sc   = rsqrtf(var + EPSV) * w[col];
        g_scale[col] = sc;
        g_shift[col] = b[col] - mean * sc;
    }
}

// fold BN into W1; write TRANSPOSED [n][k] fp16
__global__ void fold_kernel(int K, const float* __restrict__ W1,
                            const float* __restrict__ b1) {
    int j = blockIdx.x * blockDim.x + threadIdx.x;
    if (j >= HID) return;
    float acc = b1[j];
    for (int k = 0; k < K; k++) {
        float wv = W1[(long)k * HID + j];
        acc += g_shift[k] * wv;
        g_W1hT[(long)j * K + k] = __float2half_rn(wv * g_scale[k]);
    }
    g_b1p[j] = acc;
}

// W2 -> transposed [n][k] fp16
__global__ void w2cvt_kernel(const float* __restrict__ W2) {
    int i = blockIdx.x * blockDim.x + threadIdx.x;
    if (i >= D * HID) return;
    int n = i >> 9, k = i & 511;
    g_W2h[i] = __float2half_rn(W2[(long)k * D + n]);
}

// ---------------- warp-tile compute: 32(m) x 64(n) x 64(k) -------------------
// A smem [m][k], B smem [n][k]; both NON-trans ldmatrix.
__device__ __forceinline__ void compute_tile64(float (&acc)[2][8][4],
                                               uint32_t sA, uint32_t sB,
                                               int wm, int wn, int lane) {
    #pragma unroll
    for (int kk = 0; kk < 64; kk += 16) {
        uint32_t a[2][4];
        #pragma unroll
        for (int mi = 0; mi < 2; mi++) {
            uint32_t addr = sA + (uint32_t)((wm + mi * 16 + (lane & 15)) * ROWB
                                            + kk * 2 + ((lane >> 4) & 1) * 16);
            ldmx4(a[mi], addr);
        }
        uint32_t b[4][4];
        #pragma unroll
        for (int nt = 0; nt < 4; nt++) {
            int nr = wn + nt * 16 + (lane & 7) + ((lane >> 4) & 1) * 8;
            int kof = kk + ((lane >> 3) & 1) * 8;
            ldmx4(b[nt], sB + (uint32_t)(nr * ROWB + kof * 2));
        }
        #pragma unroll
        for (int mi = 0; mi < 2; mi++)
            #pragma unroll
            for (int nt = 0; nt < 4; nt++) {
                mma16(acc[mi][nt * 2 + 0], a[mi], &b[nt][0]);
                mma16(acc[mi][nt * 2 + 1], a[mi], &b[nt][2]);
            }
    }
}

// ---------------- GEMM1: g_H = gelu(X @ W1 + b1) ------------------------------
// MODE 0: K=256, X[m] = [nodes_h[m], msg_h[m]]
// MODE 1: K=384, X[m] = [no_h[src[m]], no_h[dst[m]], edges_h[m]]
// CTA tile 128 x 256, 512 threads (16 warps, 4m x 4n), BK=64, all-cp.async.
#define G1_SMEM (2 * ATILE + 2 * BTILE1 + 1024)

template <int MODE, int K>
__global__ __launch_bounds__(512, 1)
void gemm1_hmma(const int* __restrict__ graph, int M) {
    extern __shared__ __align__(16) char smem[];
    uint32_t base = smem_u32(smem);
    uint32_t sA[2] = { base,              base + ATILE };
    uint32_t sB[2] = { base + 2 * ATILE,  base + 2 * ATILE + BTILE1 };
    float* sBias = (float*)(smem + 2 * ATILE + 2 * BTILE1);

    const int tid = threadIdx.x, lane = tid & 31, wid = tid >> 5;
    const int wm = (wid & 3) * 32, wn = (wid >> 2) * 64;
    const int rowBase = blockIdx.y * 128;
    const int nBase = blockIdx.x * 256;
    const int S = K / 64;

    if (tid < 256) sBias[tid] = g_b1p[nBase + tid];

    // A fill: 4 threads/row, 32B (16 halves) each
    const int rA = tid >> 2, q4 = tid & 3;
    const int mA = rowBase + rA;
    const int mc = (mA < M) ? mA : (M - 1);
    int vsrc = 0, vdst = 0;
    if (MODE == 1) { vsrc = graph[mc]; vdst = graph[N_EDGES + mc]; }
    // B fill: 2 threads/row, 64B each
    const int rB = tid >> 1, h2 = tid & 1;

    float acc[2][8][4];
    #pragma unroll
    for (int i = 0; i < 2; i++)
        #pragma unroll
        for (int j = 0; j < 8; j++)
            #pragma unroll
            for (int c = 0; c < 4; c++) acc[i][j][c] = 0.f;

    auto fill = [&](int s, int buf) {
        int khalf = s * 64 + q4 * 16;
        int seg = khalf >> 7, l = khalf & 127;
        const __half* p;
        if (MODE == 0) {
            p = (seg == 0 ? g_nodes_h + (size_t)mc * D : g_msg_h + (size_t)mc * D) + l;
        } else {
            p = (seg == 0 ? g_no_h + (size_t)vsrc * D
               : seg == 1 ? g_no_h + (size_t)vdst * D
                          : g_edges_h + (size_t)mc * D) + l;
        }
        uint32_t dA = sA[buf] + (uint32_t)(rA * ROWB + q4 * 32);
        cp16s(dA,      p);
        cp16s(dA + 16, p + 8);
        const __half* srcB = g_W1hT + (size_t)(nBase + rB) * K + s * 64 + h2 * 32;
        uint32_t dB = sB[buf] + (uint32_t)(rB * ROWB + h2 * 64);
        #pragma unroll
        for (int q = 0; q < 4; q++) cp16s(dB + 16 * q, srcB + 8 * q);
        CP_COMMIT();
    };

    fill(0, 0);
    for (int s = 0; s < S; s++) {
        int buf = s & 1;
        CP_WAIT0();
        __syncthreads();
        if (s + 1 < S) fill(s + 1, buf ^ 1);
        compute_tile64(acc, sA[buf], sB[buf], wm, wn, lane);
    }

    // epilogue: bias + exact gelu -> fp16 g_H
    const int g = lane >> 2, tg = lane & 3;
    #pragma unroll
    for (int mi = 0; mi < 2; mi++) {
        int row0 = rowBase + wm + mi * 16 + g;
        #pragma unroll
        for (int ni = 0; ni < 8; ni++) {
            int c0 = wn + ni * 8 + tg * 2;
            int col = nBase + c0;
            float b0 = sBias[c0], b1 = sBias[c0 + 1];
            if (row0 < M) {
                __half2 hv = __floats2half2_rn(gelu_exact(acc[mi][ni][0] + b0),
                                               gelu_exact(acc[mi][ni][1] + b1));
                *(__half2*)(g_H + (size_t)row0 * HID + col) = hv;
            }
            if (row0 + 8 < M) {
                __half2 hv = __floats2half2_rn(gelu_exact(acc[mi][ni][2] + b0),
                                               gelu_exact(acc[mi][ni][3] + b1));
                *(__half2*)(g_H + (size_t)(row0 + 8) * HID + col) = hv;
            }
        }
    }
}

// ---------------- GEMM2: out = g_H @ W2 + b2 + res ----------------------------
// CTA tile 128 x 128, 256 threads, BK=64.
#define G2_SMEM (2 * ATILE + 2 * BTILE2 + 512)

__global__ __launch_bounds__(256, 2)
void gemm2_hmma(const float* __restrict__ b2,
                const float* __restrict__ res,
                float* __restrict__ out,
                int M) {
    extern __shared__ __align__(16) char smem[];
    uint32_t base = smem_u32(smem);
    uint32_t sA[2] = { base,              base + ATILE };
    uint32_t sB[2] = { base + 2 * ATILE,  base + 2 * ATILE + BTILE2 };
    float* sBias = (float*)(smem + 2 * ATILE + 2 * BTILE2);

    const int tid = threadIdx.x, lane = tid & 31, wid = tid >> 5;
    const int wm = (wid & 3) * 32, wn = (wid >> 2) * 64;
    const int rowBase = blockIdx.y * 128;
    const int S = HID / 64;   // 8

    if (tid < 128) sBias[tid] = b2[tid];

    const int r = tid >> 1, h2 = tid & 1;
    const int mA = rowBase + r;
    const int mc = (mA < M) ? mA : (M - 1);

    float acc[2][8][4];
    #pragma unroll
    for (int i = 0; i < 2; i++)
        #pragma unroll
        for (int j = 0; j < 8; j++)
            #pragma unroll
            for (int c = 0; c < 4; c++) acc[i][j][c] = 0.f;

    auto fill = [&](int s, int buf) {
        const __half* srcA = g_H + (size_t)mc * HID + s * 64 + h2 * 32;
        uint32_t dA = sA[buf] + (uint32_t)(r * ROWB + h2 * 64);
        #pragma unroll
        for (int q = 0; q < 4; q++) cp16s(dA + 16 * q, srcA + 8 * q);
        const __half* srcB = g_W2h + (size_t)r * HID + s * 64 + h2 * 32;
        uint32_t dB = sB[buf] + (uint32_t)(r * ROWB + h2 * 64);
        #pragma unroll
        for (int q = 0; q < 4; q++) cp16s(dB + 16 * q, srcB + 8 * q);
        CP_COMMIT();
    };

    fill(0, 0);
    for (int s = 0; s < S; s++) {
        int buf = s & 1;
        CP_WAIT0();
        __syncthreads();
        if (s + 1 < S) fill(s + 1, buf ^ 1);
        compute_tile64(acc, sA[buf], sB[buf], wm, wn, lane);
    }

    const int g = lane >> 2, tg = lane & 3;
    #pragma unroll
    for (int mi = 0; mi < 2; mi++) {
        int row0 = rowBase + wm + mi * 16 + g;
        #pragma unroll
        for (int ni = 0; ni < 8; ni++) {
            int col = wn + ni * 8 + tg * 2;
            float b0 = sBias[col], b1 = sBias[col + 1];
            if (row0 < M) {
                long o = (long)row0 * D + col;
                out[o]     = acc[mi][ni][0] + b0 + res[o];
                out[o + 1] = acc[mi][ni][1] + b1 + res[o + 1];
            }
            if (row0 + 8 < M) {
                long o = (long)(row0 + 8) * D + col;
                out[o]     = acc[mi][ni][2] + b0 + res[o];
                out[o + 1] = acc[mi][ni][3] + b1 + res[o + 1];
            }
        }
    }
}

// ---------------- launch -----------------------------------------------------
extern "C" void kernel_launch(void* const* d_in, const int* in_sizes, int n_in,
                              void* d_out, int out_size) {
    const float* nodes = (const float*)d_in[0];
    const float* edges = (const float*)d_in[1];
    const int*   graph = (const int*)  d_in[2];
    const float* nnw   = (const float*)d_in[3];
    const float* nnb   = (const float*)d_in[4];
    const float* enw   = (const float*)d_in[5];
    const float* enb   = (const float*)d_in[6];
    const float* Wn1   = (const float*)d_in[7];
    const float* bn1   = (const float*)d_in[8];
    const float* Wn2   = (const float*)d_in[9];
    const float* bn2   = (const float*)d_in[10];
    const float* We1   = (const float*)d_in[11];
    const float* be1   = (const float*)d_in[12];
    const float* We2   = (const float*)d_in[13];
    const float* be2   = (const float*)d_in[14];

    float* out_nodes = (float*)d_out;
    float* out_edges = out_nodes + (long)N_NODES * D;

    cudaFuncSetAttribute(gemm1_hmma<0, KN>, cudaFuncAttributeMaxDynamicSharedMemorySize, G1_SMEM);
    cudaFuncSetAttribute(gemm1_hmma<1, KE>, cudaFuncAttributeMaxDynamicSharedMemorySize, G1_SMEM);
    cudaFuncSetAttribute(gemm2_hmma,        cudaFuncAttributeMaxDynamicSharedMemorySize, G2_SMEM);

    __half *d_nodes_h, *d_msg_h, *d_no_h, *d_edges_h;
    float* d_msg;
    cudaGetSymbolAddress((void**)&d_nodes_h, g_nodes_h);
    cudaGetSymbolAddress((void**)&d_msg_h,   g_msg_h);
    cudaGetSymbolAddress((void**)&d_no_h,    g_no_h);
    cudaGetSymbolAddress((void**)&d_edges_h, g_edges_h);
    cudaGetSymbolAddress((void**)&d_msg,     g_msg);

    const long NN = (long)N_NODES * D, NE = (long)N_EDGES * D;

    // 1) msg = segment_sum(edges, dst); fp16 mirrors of static inputs
    zero_msg_kernel<<<(N_NODES * D / 4 + 255) / 256, 256>>>();
    scatter_kernel<<<(int)((NE + 255) / 256), 256>>>(edges, graph);
    cvt_h_kernel<<<(int)((NE / 4 + 255) / 256), 256>>>(edges, d_edges_h, NE);
    cvt_h_kernel<<<(int)((NN / 4 + 255) / 256), 256>>>(nodes, d_nodes_h, NN);
    cvt_h_kernel<<<(int)((NN / 4 + 255) / 256), 256>>>(d_msg, d_msg_h, NN);

    // 2) node batchnorm stats -> fold into W1
    node_stats_partial<<<STAT_BLOCKS, KN>>>(nodes);
    stats_finalize<<<KN, STAT_BLOCKS>>>(KN, 1.f / N_NODES, nnw, nnb);
    fold_kernel<<<(HID + 255) / 256, 256>>>(KN, Wn1, bn1);
    w2cvt_kernel<<<(D * HID + 255) / 256, 256>>>(Wn2);

    // 3) node MLP
    {
        dim3 g1(2, (N_NODES + 127) / 128);
        gemm1_hmma<0, KN><<<g1, 512, G1_SMEM>>>(nullptr, N_NODES);
        dim3 g2(1, (N_NODES + 127) / 128);
        gemm2_hmma<<<g2, 256, G2_SMEM>>>(bn2, nodes, out_nodes, N_NODES);
    }
    cvt_h_kernel<<<(int)((NN / 4 + 255) / 256), 256>>>(out_nodes, d_no_h, NN);

    // 4) edge batchnorm stats -> fold into W1
    edge_stats_partial<<<STAT_BLOCKS, KE>>>(out_nodes, edges, graph);
    stats_finalize<<<KE, STAT_BLOCKS>>>(KE, 1.f / N_EDGES, enw, enb);
    fold_kernel<<<(HID + 255) / 256, 256>>>(KE, We1, be1);
    w2cvt_kernel<<<(D * HID + 255) / 256, 256>>>(We2);

    // 5) edge MLP
    {
        dim3 g1(2, (N_EDGES + 127) / 128);
        gemm1_hmma<1, KE><<<g1, 512, G1_SMEM>>>(graph, N_EDGES);
        dim3 g2(1, (N_EDGES + 127) / 128);
        gemm2_hmma<<<g2, 256, G2_SMEM>>>(be2, edges, out_edges, N_EDGES);
    }
}